// round 4
// baseline (speedup 1.0000x reference)
#include <cuda_runtime.h>
#include <math.h>

// Fixed problem shapes
constexpr int S_ = 128, B_ = 64, I_ = 1024, H_ = 1024, O_ = 1024, T_ = 64;
constexpr int G_ = 4 * H_;          // 4096
constexpr int NB = 148;             // 1 CTA per SM -> co-residency guaranteed
constexpr int NT = 256;
constexpr int NTHREADS = NB * NT;

// ---------------- static device scratch (no runtime allocation) ----------------
__device__ float d_P[(size_t)S_ * B_ * G_];    // batched input projections
__device__ float d_ys0[(size_t)S_ * B_ * H_];  // encoder layer0 outputs
__device__ float d_h[2 * B_ * H_];
__device__ float d_c[2 * B_ * H_];
__device__ float d_part[8 * B_ * O_];          // split partials (2*B*G == 8*B*O floats)
__device__ float d_x[B_ * I_];                 // decoder autoregressive input
__device__ unsigned g_bar = 0;
__device__ unsigned g_gen = 0;

// ---------------- grid-wide barrier ----------------
__device__ __forceinline__ void gridbar() {
    __syncthreads();
    if (threadIdx.x == 0) {
        __threadfence();
        unsigned gen = *(volatile unsigned*)&g_gen;
        if (atomicAdd(&g_bar, 1) == NB - 1) {
            g_bar = 0;
            __threadfence();
            atomicAdd(&g_gen, 1);
        } else {
            while (*(volatile unsigned*)&g_gen == gen) { }
        }
        __threadfence();
    }
    __syncthreads();
}

// packed fp32x2 FMA: d = a*b + c elementwise on 2-float lanes
__device__ __forceinline__ unsigned long long ffma2_(unsigned long long a,
                                                     unsigned long long b,
                                                     unsigned long long c) {
    unsigned long long d;
    asm("fma.rn.f32x2 %0, %1, %2, %3;" : "=l"(d) : "l"(a), "l"(b), "l"(c));
    return d;
}

// ---------------- 64x64 fp32 GEMM tile: C = A[64,K] @ W[64,K]^T ----------------
// Smem tiles [64 rows][36 floats] (row stride 144B: 16B-aligned, bank-step 4).
// Thread (tx=tid&15, ty=tid>>4) owns rows {ty+16i}, cols {tx+16j}.
// K packed in fp32x2 lanes (even/odd), halves summed at writeback.
__device__ __forceinline__ void gemm_tile64(
    const float* __restrict__ A, int lda,
    const float* __restrict__ W, int ldw,
    float* __restrict__ C, int ldc, int K,
    float* As, float* Ws)
{
    const int tid = threadIdx.x;
    const int tx = tid & 15, ty = tid >> 4;
    const int lrow = tid >> 3;         // 0..31 (loader row, +32 for q=1)
    const int lc4  = tid & 7;          // 0..7  (loader 16B chunk along K)

    unsigned long long acc[4][4];
#pragma unroll
    for (int i = 0; i < 4; i++)
#pragma unroll
        for (int j = 0; j < 4; j++) acc[i][j] = 0ULL;

    // prefetch kb = 0
    float4 pa0 = *reinterpret_cast<const float4*>(A + (size_t)lrow * lda + lc4 * 4);
    float4 pa1 = *reinterpret_cast<const float4*>(A + (size_t)(lrow + 32) * lda + lc4 * 4);
    float4 pw0 = *reinterpret_cast<const float4*>(W + (size_t)lrow * ldw + lc4 * 4);
    float4 pw1 = *reinterpret_cast<const float4*>(W + (size_t)(lrow + 32) * ldw + lc4 * 4);

    for (int kb = 0; kb < K; kb += 32) {
        *reinterpret_cast<float4*>(As + lrow * 36 + lc4 * 4) = pa0;
        *reinterpret_cast<float4*>(As + (lrow + 32) * 36 + lc4 * 4) = pa1;
        *reinterpret_cast<float4*>(Ws + lrow * 36 + lc4 * 4) = pw0;
        *reinterpret_cast<float4*>(Ws + (lrow + 32) * 36 + lc4 * 4) = pw1;
        __syncthreads();

        if (kb + 32 < K) {
            const float* An = A + kb + 32;
            const float* Wn = W + kb + 32;
            pa0 = *reinterpret_cast<const float4*>(An + (size_t)lrow * lda + lc4 * 4);
            pa1 = *reinterpret_cast<const float4*>(An + (size_t)(lrow + 32) * lda + lc4 * 4);
            pw0 = *reinterpret_cast<const float4*>(Wn + (size_t)lrow * ldw + lc4 * 4);
            pw1 = *reinterpret_cast<const float4*>(Wn + (size_t)(lrow + 32) * ldw + lc4 * 4);
        }

#pragma unroll
        for (int kc = 0; kc < 8; kc++) {
            ulonglong2 av[4], wv[4];
#pragma unroll
            for (int i = 0; i < 4; i++)
                av[i] = *reinterpret_cast<const ulonglong2*>(As + (ty + 16 * i) * 36 + kc * 4);
#pragma unroll
            for (int j = 0; j < 4; j++)
                wv[j] = *reinterpret_cast<const ulonglong2*>(Ws + (tx + 16 * j) * 36 + kc * 4);
#pragma unroll
            for (int i = 0; i < 4; i++)
#pragma unroll
                for (int j = 0; j < 4; j++) {
                    acc[i][j] = ffma2_(av[i].x, wv[j].x, acc[i][j]);
                    acc[i][j] = ffma2_(av[i].y, wv[j].y, acc[i][j]);
                }
        }
        __syncthreads();
    }

#pragma unroll
    for (int i = 0; i < 4; i++)
#pragma unroll
        for (int j = 0; j < 4; j++) {
            unsigned long long v = acc[i][j];
            float lo = __int_as_float((int)(unsigned)(v & 0xffffffffULL));
            float hi = __int_as_float((int)(unsigned)(v >> 32));
            C[(size_t)(ty + 16 * i) * ldc + (tx + 16 * j)] = lo + hi;
        }
}

__device__ __forceinline__ float sig_(float x) { return 1.f / (1.f + __expf(-x)); }

// pointwise LSTM gates: sum 2 split partials (+ optional precomputed input proj)
__device__ void gates_fn(const float* __restrict__ proj, const float* __restrict__ bias,
                         float* __restrict__ h, float* __restrict__ c,
                         float* __restrict__ ysave)
{
    for (int idx = blockIdx.x * NT + threadIdx.x; idx < B_ * H_; idx += NTHREADS) {
        int b = idx >> 10, n = idx & 1023;
        float gi = bias[n], gf = bias[H_ + n], gg = bias[2 * H_ + n], go = bias[3 * H_ + n];
        if (proj) {
            const float* p = proj + (size_t)b * G_;
            gi += p[n]; gf += p[H_ + n]; gg += p[2 * H_ + n]; go += p[3 * H_ + n];
        }
#pragma unroll
        for (int s = 0; s < 2; s++) {
            const float* p = d_part + (size_t)s * B_ * G_ + (size_t)b * G_;
            gi += p[n]; gf += p[H_ + n]; gg += p[2 * H_ + n]; go += p[3 * H_ + n];
        }
        float cv = sig_(gf) * c[idx] + sig_(gi) * tanhf(gg);
        float hv = sig_(go) * tanhf(cv);
        c[idx] = cv;
        h[idx] = hv;
        if (ysave) ysave[idx] = hv;
    }
}

// ---------------- whole seq2seq: ONE persistent kernel ----------------
__global__ void __launch_bounds__(NT)
seq2seq_kernel(const float* __restrict__ x_seq,
               const float* __restrict__ enc_wih, const float* __restrict__ enc_whh,
               const float* __restrict__ enc_b,
               const float* __restrict__ dec_wih, const float* __restrict__ dec_whh,
               const float* __restrict__ dec_b,
               const float* __restrict__ lin_w, const float* __restrict__ lin_b,
               float* __restrict__ out)
{
    __shared__ float As[64 * 36];
    __shared__ float Ws[64 * 36];
    const int bid = blockIdx.x, tid = threadIdx.x;

    // init
    for (int i = bid * NT + tid; i < 2 * B_ * H_; i += NTHREADS) { d_h[i] = 0.f; d_c[i] = 0.f; }
    for (int i = bid * NT + tid; i < B_ * I_; i += NTHREADS)
        d_x[i] = x_seq[(size_t)(S_ - 1) * B_ * I_ + i];
    gridbar();

    // ===== encoder: 2 stacked layers =====
    for (int l = 0; l < 2; l++) {
        const float* inp  = (l == 0) ? x_seq : d_ys0;
        const float* wih  = enc_wih + (size_t)l * G_ * I_;
        const float* whh  = enc_whh + (size_t)l * G_ * H_;
        const float* bias = enc_b + (size_t)l * G_;
        float* hl = d_h + l * B_ * H_;
        float* cl = d_c + l * B_ * H_;

        // batched input projection: P = inp @ wih^T  (M = S*B = 8192)
        for (int u = bid; u < 128 * 64; u += NB) {
            int tm = u >> 6, tn = u & 63;
            gemm_tile64(inp + (size_t)tm * 64 * I_, I_,
                        wih + (size_t)tn * 64 * I_, I_,
                        d_P + (size_t)tm * 64 * G_ + tn * 64, G_, I_, As, Ws);
        }
        gridbar();

        // recurrence: 64 N-tiles x 2 K-slices (K=512) = 128 work units
        for (int t = 0; t < S_; t++) {
            if (bid < 128) {
                int tn = bid >> 1, ks = bid & 1;
                gemm_tile64(hl + ks * 512, H_,
                            whh + (size_t)tn * 64 * H_ + ks * 512, H_,
                            d_part + (size_t)ks * B_ * G_ + tn * 64, G_, 512, As, Ws);
            }
            gridbar();
            gates_fn(d_P + (size_t)t * B_ * G_, bias, hl, cl,
                     (l == 0) ? (d_ys0 + (size_t)t * B_ * H_) : nullptr);
            gridbar();
        }
    }

    // ===== autoregressive decoder =====
    float* h0 = d_h;             float* c0 = d_c;
    float* h1 = d_h + B_ * H_;   float* c1 = d_c + B_ * H_;

    for (int t = 0; t < T_; t++) {
        // layer 0: ks=0 -> x @ wih^T, ks=1 -> h0 @ whh^T (each K=1024)
        if (bid < 128) {
            int tn = bid >> 1, ks = bid & 1;
            const float* Aptr = ks ? h0 : d_x;
            const float* Wptr = ks ? (dec_whh + (size_t)tn * 64 * H_)
                                   : (dec_wih + (size_t)tn * 64 * I_);
            gemm_tile64(Aptr, 1024, Wptr, 1024,
                        d_part + (size_t)ks * B_ * G_ + tn * 64, G_, 1024, As, Ws);
        }
        gridbar();
        gates_fn(nullptr, dec_b, h0, c0, nullptr);
        gridbar();

        // layer 1: input = h0
        if (bid < 128) {
            int tn = bid >> 1, ks = bid & 1;
            const float* Aptr = ks ? h1 : h0;
            const float* Wptr = ks ? (dec_whh + (size_t)G_ * H_ + (size_t)tn * 64 * H_)
                                   : (dec_wih + (size_t)G_ * I_ + (size_t)tn * 64 * I_);
            gemm_tile64(Aptr, 1024, Wptr, 1024,
                        d_part + (size_t)ks * B_ * G_ + tn * 64, G_, 1024, As, Ws);
        }
        gridbar();
        gates_fn(nullptr, dec_b + G_, h1, c1, nullptr);
        gridbar();

        // output linear: 16 N-tiles x 8 K-slices (K=128) = 128 units
        if (bid < 128) {
            int tn = bid >> 3, ks = bid & 7;
            gemm_tile64(h1 + ks * 128, H_,
                        lin_w + (size_t)tn * 64 * H_ + ks * 128, H_,
                        d_part + (size_t)ks * B_ * O_ + tn * 64, O_, 128, As, Ws);
        }
        gridbar();
        for (int idx = bid * NT + tid; idx < B_ * O_; idx += NTHREADS) {
            int b = idx >> 10, n = idx & 1023;
            float v = lin_b[n];
#pragma unroll
            for (int s = 0; s < 8; s++)
                v += d_part[(size_t)s * B_ * O_ + (size_t)b * O_ + n];
            out[(size_t)b * T_ * O_ + (size_t)t * O_ + n] = v;
            d_x[idx] = v;
        }
        gridbar();
    }
}

// ---------------- driver: single launch => single graph node ----------------
extern "C" void kernel_launch(void* const* d_in, const int* in_sizes, int n_in,
                              void* d_out, int out_size)
{
    seq2seq_kernel<<<NB, NT>>>(
        (const float*)d_in[0], (const float*)d_in[1], (const float*)d_in[2],
        (const float*)d_in[3], (const float*)d_in[4], (const float*)d_in[5],
        (const float*)d_in[6], (const float*)d_in[7], (const float*)d_in[8],
        (float*)d_out);
}

// round 5
// speedup vs baseline: 1.6188x; 1.6188x over previous
#include <cuda_runtime.h>
#include <math.h>

// Fixed problem shapes
constexpr int S_ = 128, B_ = 64, I_ = 1024, H_ = 1024, O_ = 1024, T_ = 64;
constexpr int G_ = 4 * H_;          // 4096
constexpr int NB = 148;             // 1 CTA per SM -> co-residency guaranteed
constexpr int NT = 512;
constexpr int NTHREADS = NB * NT;

// ---------------- static device scratch ----------------
__device__ float d_P[(size_t)S_ * B_ * G_];    // batched input projections
__device__ float d_ys0[(size_t)S_ * B_ * H_];  // encoder layer0 outputs
__device__ float d_h[2 * B_ * H_];
__device__ float d_c[2 * B_ * H_];
__device__ float d_part[4 * B_ * G_];          // split-K partials (== 16*B*O floats)
__device__ float d_x[B_ * I_];                 // decoder autoregressive input
__device__ unsigned g_bar = 0;
__device__ unsigned g_gen = 0;

// ---------------- grid-wide barrier ----------------
__device__ __forceinline__ void gridbar() {
    __syncthreads();
    if (threadIdx.x == 0) {
        __threadfence();
        unsigned gen = *(volatile unsigned*)&g_gen;
        if (atomicAdd(&g_bar, 1) == NB - 1) {
            g_bar = 0;
            __threadfence();
            atomicAdd(&g_gen, 1);
        } else {
            while (*(volatile unsigned*)&g_gen == gen) { }
        }
        __threadfence();
    }
    __syncthreads();
}

// packed fp32x2 FMA
__device__ __forceinline__ unsigned long long ffma2_(unsigned long long a,
                                                     unsigned long long b,
                                                     unsigned long long c) {
    unsigned long long d;
    asm("fma.rn.f32x2 %0, %1, %2, %3;" : "=l"(d) : "l"(a), "l"(b), "l"(c));
    return d;
}

// ---------------- 64x128 fp32 GEMM tile: C = A[64,K] @ W[128,K]^T ----------------
// 512 threads. Register tile i=8 (rows, warp-broadcast) x j=2 (cols, per-lane).
// As: row stride 36 floats (16B-aligned stores; reads are broadcast).
// Ws: row stride 34 floats (LDS.64 conflict-free per half-warp phase).
// K packed into fp32x2 lanes; halves summed at writeback.
__device__ __forceinline__ void gemm_tile(
    const float* __restrict__ A, int lda,
    const float* __restrict__ W, int ldw,
    float* __restrict__ C, int ldc, int K,
    float* As, float* Ws)
{
    const int tid = threadIdx.x;
    const int tx = tid & 63;            // col group: cols {tx, tx+64}
    const int ty = tid >> 6;            // row group (warp-constant): rows {ty+8i}
    const int lrow = tid >> 3;          // loader row 0..63
    const int lc4  = tid & 7;           // loader 16B chunk along K

    unsigned long long acc[8][2];
#pragma unroll
    for (int i = 0; i < 8; i++) { acc[i][0] = 0ULL; acc[i][1] = 0ULL; }

    // prefetch kb = 0
    float4 pa  = *reinterpret_cast<const float4*>(A + (size_t)lrow * lda + lc4 * 4);
    float4 pw0 = *reinterpret_cast<const float4*>(W + (size_t)lrow * ldw + lc4 * 4);
    float4 pw1 = *reinterpret_cast<const float4*>(W + (size_t)(lrow + 64) * ldw + lc4 * 4);

    for (int kb = 0; kb < K; kb += 32) {
        *reinterpret_cast<float4*>(As + lrow * 36 + lc4 * 4) = pa;
        {   // Ws stride 34 floats: 8B-aligned -> two float2 stores per float4
            float* wp0 = Ws + lrow * 34 + lc4 * 4;
            *reinterpret_cast<float2*>(wp0)     = make_float2(pw0.x, pw0.y);
            *reinterpret_cast<float2*>(wp0 + 2) = make_float2(pw0.z, pw0.w);
            float* wp1 = Ws + (lrow + 64) * 34 + lc4 * 4;
            *reinterpret_cast<float2*>(wp1)     = make_float2(pw1.x, pw1.y);
            *reinterpret_cast<float2*>(wp1 + 2) = make_float2(pw1.z, pw1.w);
        }
        __syncthreads();

        if (kb + 32 < K) {
            const float* An = A + kb + 32;
            const float* Wn = W + kb + 32;
            pa  = *reinterpret_cast<const float4*>(An + (size_t)lrow * lda + lc4 * 4);
            pw0 = *reinterpret_cast<const float4*>(Wn + (size_t)lrow * ldw + lc4 * 4);
            pw1 = *reinterpret_cast<const float4*>(Wn + (size_t)(lrow + 64) * ldw + lc4 * 4);
        }

#pragma unroll
        for (int kk = 0; kk < 16; kk++) {   // 2 K-values per iteration (one f32x2)
            unsigned long long av[8], wv[2];
#pragma unroll
            for (int i = 0; i < 8; i++)     // broadcast within warp
                av[i] = *reinterpret_cast<const unsigned long long*>(
                    As + (ty + 8 * i) * 36 + kk * 2);
#pragma unroll
            for (int j = 0; j < 2; j++)     // per-lane, conflict-free
                wv[j] = *reinterpret_cast<const unsigned long long*>(
                    Ws + (tx + 64 * j) * 34 + kk * 2);
#pragma unroll
            for (int i = 0; i < 8; i++) {
                acc[i][0] = ffma2_(av[i], wv[0], acc[i][0]);
                acc[i][1] = ffma2_(av[i], wv[1], acc[i][1]);
            }
        }
        __syncthreads();
    }

#pragma unroll
    for (int i = 0; i < 8; i++)
#pragma unroll
        for (int j = 0; j < 2; j++) {
            unsigned long long v = acc[i][j];
            float lo = __int_as_float((int)(unsigned)(v & 0xffffffffULL));
            float hi = __int_as_float((int)(unsigned)(v >> 32));
            C[(size_t)(ty + 8 * i) * ldc + (tx + 64 * j)] = lo + hi;
        }
}

__device__ __forceinline__ float sig_(float x) { return 1.f / (1.f + __expf(-x)); }

// pointwise LSTM gates: sum 4 split-K partials (+ optional precomputed input proj)
__device__ void gates_fn(const float* __restrict__ proj, const float* __restrict__ bias,
                         float* __restrict__ h, float* __restrict__ c,
                         float* __restrict__ ysave)
{
    for (int idx = blockIdx.x * NT + threadIdx.x; idx < B_ * H_; idx += NTHREADS) {
        int b = idx >> 10, n = idx & 1023;
        float gi = bias[n], gf = bias[H_ + n], gg = bias[2 * H_ + n], go = bias[3 * H_ + n];
        if (proj) {
            const float* p = proj + (size_t)b * G_;
            gi += p[n]; gf += p[H_ + n]; gg += p[2 * H_ + n]; go += p[3 * H_ + n];
        }
#pragma unroll
        for (int s = 0; s < 4; s++) {
            const float* p = d_part + (size_t)s * B_ * G_ + (size_t)b * G_;
            gi += p[n]; gf += p[H_ + n]; gg += p[2 * H_ + n]; go += p[3 * H_ + n];
        }
        float cv = sig_(gf) * c[idx] + sig_(gi) * tanhf(gg);
        float hv = sig_(go) * tanhf(cv);
        c[idx] = cv;
        h[idx] = hv;
        if (ysave) ysave[idx] = hv;
    }
}

// ---------------- whole seq2seq: ONE persistent kernel ----------------
__global__ void __launch_bounds__(NT)
seq2seq_kernel(const float* __restrict__ x_seq,
               const float* __restrict__ enc_wih, const float* __restrict__ enc_whh,
               const float* __restrict__ enc_b,
               const float* __restrict__ dec_wih, const float* __restrict__ dec_whh,
               const float* __restrict__ dec_b,
               const float* __restrict__ lin_w, const float* __restrict__ lin_b,
               float* __restrict__ out)
{
    __shared__ float As[64 * 36];     //  9.2 KB
    __shared__ float Ws[128 * 34];    // 17.4 KB
    const int bid = blockIdx.x, tid = threadIdx.x;

    // init
    for (int i = bid * NT + tid; i < 2 * B_ * H_; i += NTHREADS) { d_h[i] = 0.f; d_c[i] = 0.f; }
    for (int i = bid * NT + tid; i < B_ * I_; i += NTHREADS)
        d_x[i] = x_seq[(size_t)(S_ - 1) * B_ * I_ + i];
    gridbar();

    // ===== encoder: 2 stacked layers =====
    for (int l = 0; l < 2; l++) {
        const float* inp  = (l == 0) ? x_seq : d_ys0;
        const float* wih  = enc_wih + (size_t)l * G_ * I_;
        const float* whh  = enc_whh + (size_t)l * G_ * H_;
        const float* bias = enc_b + (size_t)l * G_;
        float* hl = d_h + l * B_ * H_;
        float* cl = d_c + l * B_ * H_;

        // batched input projection: P = inp @ wih^T  (128 M-tiles x 32 N-tiles)
        for (int u = bid; u < 128 * 32; u += NB) {
            int tm = u >> 5, tn = u & 31;
            gemm_tile(inp + (size_t)tm * 64 * I_, I_,
                      wih + (size_t)tn * 128 * I_, I_,
                      d_P + (size_t)tm * 64 * G_ + tn * 128, G_, I_, As, Ws);
        }
        gridbar();

        // recurrence: 32 N-tiles x 4 K-slices (K=256) = 128 work units
        for (int t = 0; t < S_; t++) {
            if (bid < 128) {
                int tn = bid >> 2, ks = bid & 3;
                gemm_tile(hl + ks * 256, H_,
                          whh + (size_t)tn * 128 * H_ + ks * 256, H_,
                          d_part + (size_t)ks * B_ * G_ + tn * 128, G_, 256, As, Ws);
            }
            gridbar();
            gates_fn(d_P + (size_t)t * B_ * G_, bias, hl, cl,
                     (l == 0) ? (d_ys0 + (size_t)t * B_ * H_) : nullptr);
            gridbar();
        }
    }

    // ===== autoregressive decoder =====
    float* h0 = d_h;             float* c0 = d_c;
    float* h1 = d_h + B_ * H_;   float* c1 = d_c + B_ * H_;

    for (int t = 0; t < T_; t++) {
        // layer 0: virtual K=2048 (x@wih^T ++ h0@whh^T), 4 slices of 512
        if (bid < 128) {
            int tn = bid >> 2, ks = bid & 3;
            const float* Aptr; const float* Wptr;
            if (ks < 2) { Aptr = d_x + ks * 512;
                          Wptr = dec_wih + (size_t)tn * 128 * I_ + ks * 512; }
            else        { Aptr = h0 + (ks - 2) * 512;
                          Wptr = dec_whh + (size_t)tn * 128 * H_ + (ks - 2) * 512; }
            gemm_tile(Aptr, 1024, Wptr, 1024,
                      d_part + (size_t)ks * B_ * G_ + tn * 128, G_, 512, As, Ws);
        }
        gridbar();
        gates_fn(nullptr, dec_b, h0, c0, nullptr);
        gridbar();

        // layer 1: input = h0
        if (bid < 128) {
            int tn = bid >> 2, ks = bid & 3;
            const float* Aptr; const float* Wptr;
            if (ks < 2) { Aptr = h0 + ks * 512;
                          Wptr = dec_wih + (size_t)G_ * I_ + (size_t)tn * 128 * I_ + ks * 512; }
            else        { Aptr = h1 + (ks - 2) * 512;
                          Wptr = dec_whh + (size_t)G_ * H_ + (size_t)tn * 128 * H_ + (ks - 2) * 512; }
            gemm_tile(Aptr, 1024, Wptr, 1024,
                      d_part + (size_t)ks * B_ * G_ + tn * 128, G_, 512, As, Ws);
        }
        gridbar();
        gates_fn(nullptr, dec_b + G_, h1, c1, nullptr);
        gridbar();

        // output linear: 8 N-tiles x 16 K-slices (K=64) = 128 units
        if (bid < 128) {
            int tn = bid >> 4, ks = bid & 15;
            gemm_tile(h1 + ks * 64, H_,
                      lin_w + (size_t)tn * 128 * H_ + ks * 64, H_,
                      d_part + (size_t)ks * B_ * O_ + tn * 128, O_, 64, As, Ws);
        }
        gridbar();
        for (int idx = bid * NT + tid; idx < B_ * O_; idx += NTHREADS) {
            int b = idx >> 10, n = idx & 1023;
            float v = lin_b[n];
#pragma unroll
            for (int s = 0; s < 16; s++)
                v += d_part[(size_t)s * B_ * O_ + (size_t)b * O_ + n];
            out[(size_t)b * T_ * O_ + (size_t)t * O_ + n] = v;
            d_x[idx] = v;
        }
        gridbar();
    }
}

// ---------------- driver: single launch => single graph node ----------------
extern "C" void kernel_launch(void* const* d_in, const int* in_sizes, int n_in,
                              void* d_out, int out_size)
{
    seq2seq_kernel<<<NB, NT>>>(
        (const float*)d_in[0], (const float*)d_in[1], (const float*)d_in[2],
        (const float*)d_in[3], (const float*)d_in[4], (const float*)d_in[5],
        (const float*)d_in[6], (const float*)d_in[7], (const float*)d_in[8],
        (float*)d_out);
}

// round 10
// speedup vs baseline: 1.6662x; 1.0293x over previous
#include <cuda_runtime.h>
#include <math.h>

// Fixed problem shapes
constexpr int S_ = 128, B_ = 64, I_ = 1024, H_ = 1024, O_ = 1024, T_ = 64;
constexpr int G_ = 4 * H_;          // 4096
constexpr int NB = 148;             // 1 CTA per SM -> co-residency guaranteed
constexpr int NT = 512;
constexpr int NTHREADS = NB * NT;

// ---------------- static device scratch ----------------
__device__ float d_P[(size_t)S_ * B_ * G_];    // batched input projections
__device__ float d_ys0[(size_t)S_ * B_ * H_];  // encoder layer0 outputs
__device__ float d_h[2 * B_ * H_];
__device__ float d_c[2 * B_ * H_];
__device__ float d_part[4 * B_ * G_];          // split-K partials (== 16*B*O floats)
__device__ float d_x[B_ * I_];                 // decoder autoregressive input
__device__ unsigned g_bar = 0;
__device__ unsigned g_gen = 0;

// ---------------- grid-wide barrier ----------------
__device__ __forceinline__ void gridbar() {
    __syncthreads();
    if (threadIdx.x == 0) {
        __threadfence();
        unsigned gen = *(volatile unsigned*)&g_gen;
        if (atomicAdd(&g_bar, 1) == NB - 1) {
            g_bar = 0;
            __threadfence();
            atomicAdd(&g_gen, 1);
        } else {
            while (*(volatile unsigned*)&g_gen == gen) { }
        }
        __threadfence();
    }
    __syncthreads();
}

// packed fp32x2 FMA
__device__ __forceinline__ unsigned long long ffma2_(unsigned long long a,
                                                     unsigned long long b,
                                                     unsigned long long c) {
    unsigned long long d;
    asm("fma.rn.f32x2 %0, %1, %2, %3;" : "=l"(d) : "l"(a), "l"(b), "l"(c));
    return d;
}

// ---------------- 64x128 fp32 GEMM tile: C = A[64,K] @ W[128,K]^T ----------------
// 512 threads. Register tile i=8 (rows, warp-broadcast) x j=2 (cols, per-lane).
// Both smem tiles: row stride 36 floats (16B-aligned; LDS.128 conflict-free:
// bank = 4*lane mod 32 distinct within each 8-lane phase).
// Double-buffered: one __syncthreads per 32-K chunk.
// K packed into fp32x2 lanes; halves summed at writeback.
constexpr int AS_STRIDE = 36;
constexpr int AS_BUF = 64 * AS_STRIDE;    // floats per A buffer
constexpr int WS_BUF = 128 * AS_STRIDE;   // floats per W buffer

__device__ __forceinline__ void gemm_tile(
    const float* __restrict__ A, int lda,
    const float* __restrict__ W, int ldw,
    float* __restrict__ C, int ldc, int K,
    float* As, float* Ws)
{
    const int tid = threadIdx.x;
    const int tx = tid & 63;            // col group: cols {tx, tx+64}
    const int ty = tid >> 6;            // row group (warp-constant): rows {ty+8i}
    const int lrow = tid >> 3;          // loader row 0..63
    const int lc4  = tid & 7;           // loader 16B chunk along K

    unsigned long long acc[8][2];
#pragma unroll
    for (int i = 0; i < 8; i++) { acc[i][0] = 0ULL; acc[i][1] = 0ULL; }

    // prologue: load + store chunk 0 into buffer 0
    float4 pa  = *reinterpret_cast<const float4*>(A + (size_t)lrow * lda + lc4 * 4);
    float4 pw0 = *reinterpret_cast<const float4*>(W + (size_t)lrow * ldw + lc4 * 4);
    float4 pw1 = *reinterpret_cast<const float4*>(W + (size_t)(lrow + 64) * ldw + lc4 * 4);
    *reinterpret_cast<float4*>(As + lrow * AS_STRIDE + lc4 * 4) = pa;
    *reinterpret_cast<float4*>(Ws + lrow * AS_STRIDE + lc4 * 4) = pw0;
    *reinterpret_cast<float4*>(Ws + (lrow + 64) * AS_STRIDE + lc4 * 4) = pw1;
    __syncthreads();

    int p = 0;
    for (int kb = 0; kb < K; kb += 32) {
        const bool more = (kb + 32 < K);
        if (more) {   // prefetch next chunk from gmem into regs
            const float* An = A + kb + 32;
            const float* Wn = W + kb + 32;
            pa  = *reinterpret_cast<const float4*>(An + (size_t)lrow * lda + lc4 * 4);
            pw0 = *reinterpret_cast<const float4*>(Wn + (size_t)lrow * ldw + lc4 * 4);
            pw1 = *reinterpret_cast<const float4*>(Wn + (size_t)(lrow + 64) * ldw + lc4 * 4);
        }

        const float* Asb = As + p * AS_BUF;
        const float* Wsb = Ws + p * WS_BUF;
#pragma unroll
        for (int k4 = 0; k4 < 8; k4++) {    // 4 K-values per iteration (LDS.128)
            ulonglong2 av[8], wv[2];
#pragma unroll
            for (int i = 0; i < 8; i++)     // warp-broadcast
                av[i] = *reinterpret_cast<const ulonglong2*>(
                    Asb + (ty + 8 * i) * AS_STRIDE + k4 * 4);
#pragma unroll
            for (int j = 0; j < 2; j++)     // per-lane, conflict-free
                wv[j] = *reinterpret_cast<const ulonglong2*>(
                    Wsb + (tx + 64 * j) * AS_STRIDE + k4 * 4);
#pragma unroll
            for (int i = 0; i < 8; i++)
#pragma unroll
                for (int j = 0; j < 2; j++) {
                    acc[i][j] = ffma2_(av[i].x, wv[j].x, acc[i][j]);
                    acc[i][j] = ffma2_(av[i].y, wv[j].y, acc[i][j]);
                }
        }

        if (more) {   // store prefetched chunk into the other buffer (no hazard:
                      // everyone still reads buffer p; sync below publishes p^1)
            float* Asn = As + (p ^ 1) * AS_BUF;
            float* Wsn = Ws + (p ^ 1) * WS_BUF;
            *reinterpret_cast<float4*>(Asn + lrow * AS_STRIDE + lc4 * 4) = pa;
            *reinterpret_cast<float4*>(Wsn + lrow * AS_STRIDE + lc4 * 4) = pw0;
            *reinterpret_cast<float4*>(Wsn + (lrow + 64) * AS_STRIDE + lc4 * 4) = pw1;
            p ^= 1;
        }
        __syncthreads();
    }

#pragma unroll
    for (int i = 0; i < 8; i++)
#pragma unroll
        for (int j = 0; j < 2; j++) {
            unsigned long long v = acc[i][j];
            float lo = __int_as_float((int)(unsigned)(v & 0xffffffffULL));
            float hi = __int_as_float((int)(unsigned)(v >> 32));
            C[(size_t)(ty + 8 * i) * ldc + (tx + 64 * j)] = lo + hi;
        }
}

__device__ __forceinline__ float sig_(float x) { return 1.f / (1.f + __expf(-x)); }

// pointwise LSTM gates: sum 4 split-K partials (+ optional precomputed input proj)
__device__ void gates_fn(const float* __restrict__ proj, const float* __restrict__ bias,
                         float* __restrict__ h, float* __restrict__ c,
                         float* __restrict__ ysave)
{
    for (int idx = blockIdx.x * NT + threadIdx.x; idx < B_ * H_; idx += NTHREADS) {
        int b = idx >> 10, n = idx & 1023;
        float gi = bias[n], gf = bias[H_ + n], gg = bias[2 * H_ + n], go = bias[3 * H_ + n];
        if (proj) {
            const float* p = proj + (size_t)b * G_;
            gi += p[n]; gf += p[H_ + n]; gg += p[2 * H_ + n]; go += p[3 * H_ + n];
        }
#pragma unroll
        for (int s = 0; s < 4; s++) {
            const float* p = d_part + (size_t)s * B_ * G_ + (size_t)b * G_;
            gi += p[n]; gf += p[H_ + n]; gg += p[2 * H_ + n]; go += p[3 * H_ + n];
        }
        float cv = sig_(gf) * c[idx] + sig_(gi) * tanhf(gg);
        float hv = sig_(go) * tanhf(cv);
        c[idx] = cv;
        h[idx] = hv;
        if (ysave) ysave[idx] = hv;
    }
}

// ---------------- whole seq2seq: ONE persistent kernel ----------------
__global__ void __launch_bounds__(NT)
seq2seq_kernel(const float* __restrict__ x_seq,
               const float* __restrict__ enc_wih, const float* __restrict__ enc_whh,
               const float* __restrict__ enc_b,
               const float* __restrict__ dec_wih, const float* __restrict__ dec_whh,
               const float* __restrict__ dec_b,
               const float* __restrict__ lin_w, const float* __restrict__ lin_b,
               float* __restrict__ out)
{
    __shared__ __align__(16) float As[2 * AS_BUF];   // 18.4 KB
    __shared__ __align__(16) float Ws[2 * WS_BUF];   // 36.9 KB
    const int bid = blockIdx.x, tid = threadIdx.x;

    // init
    for (int i = bid * NT + tid; i < 2 * B_ * H_; i += NTHREADS) { d_h[i] = 0.f; d_c[i] = 0.f; }
    for (int i = bid * NT + tid; i < B_ * I_; i += NTHREADS)
        d_x[i] = x_seq[(size_t)(S_ - 1) * B_ * I_ + i];
    gridbar();

    // ===== encoder: 2 stacked layers =====
    for (int l = 0; l < 2; l++) {
        const float* inp  = (l == 0) ? x_seq : d_ys0;
        const float* wih  = enc_wih + (size_t)l * G_ * I_;
        const float* whh  = enc_whh + (size_t)l * G_ * H_;
        const float* bias = enc_b + (size_t)l * G_;
        float* hl = d_h + l * B_ * H_;
        float* cl = d_c + l * B_ * H_;

        // batched input projection: P = inp @ wih^T  (128 M-tiles x 32 N-tiles)
        for (int u = bid; u < 128 * 32; u += NB) {
            int tm = u >> 5, tn = u & 31;
            gemm_tile(inp + (size_t)tm * 64 * I_, I_,
                      wih + (size_t)tn * 128 * I_, I_,
                      d_P + (size_t)tm * 64 * G_ + tn * 128, G_, I_, As, Ws);
        }
        gridbar();

        // recurrence: 32 N-tiles x 4 K-slices (K=256) = 128 work units
        for (int t = 0; t < S_; t++) {
            if (bid < 128) {
                int tn = bid >> 2, ks = bid & 3;
                gemm_tile(hl + ks * 256, H_,
                          whh + (size_t)tn * 128 * H_ + ks * 256, H_,
                          d_part + (size_t)ks * B_ * G_ + tn * 128, G_, 256, As, Ws);
            }
            gridbar();
            gates_fn(d_P + (size_t)t * B_ * G_, bias, hl, cl,
                     (l == 0) ? (d_ys0 + (size_t)t * B_ * H_) : nullptr);
            gridbar();
        }
    }

    // ===== autoregressive decoder =====
    float* h0 = d_h;             float* c0 = d_c;
    float* h1 = d_h + B_ * H_;   float* c1 = d_c + B_ * H_;

    for (int t = 0; t < T_; t++) {
        // layer 0: virtual K=2048 (x@wih^T ++ h0@whh^T), 4 slices of 512
        if (bid < 128) {
            int tn = bid >> 2, ks = bid & 3;
            const float* Aptr; const float* Wptr;
            if (ks < 2) { Aptr = d_x + ks * 512;
                          Wptr = dec_wih + (size_t)tn * 128 * I_ + ks * 512; }
            else        { Aptr = h0 + (ks - 2) * 512;
                          Wptr = dec_whh + (size_t)tn * 128 * H_ + (ks - 2) * 512; }
            gemm_tile(Aptr, 1024, Wptr, 1024,
                      d_part + (size_t)ks * B_ * G_ + tn * 128, G_, 512, As, Ws);
        }
        gridbar();
        gates_fn(nullptr, dec_b, h0, c0, nullptr);
        gridbar();

        // layer 1: input = h0
        if (bid < 128) {
            int tn = bid >> 2, ks = bid & 3;
            const float* Aptr; const float* Wptr;
            if (ks < 2) { Aptr = h0 + ks * 512;
                          Wptr = dec_wih + (size_t)G_ * I_ + (size_t)tn * 128 * I_ + ks * 512; }
            else        { Aptr = h1 + (ks - 2) * 512;
                          Wptr = dec_whh + (size_t)G_ * H_ + (size_t)tn * 128 * H_ + (ks - 2) * 512; }
            gemm_tile(Aptr, 1024, Wptr, 1024,
                      d_part + (size_t)ks * B_ * G_ + tn * 128, G_, 512, As, Ws);
        }
        gridbar();
        gates_fn(nullptr, dec_b + G_, h1, c1, nullptr);
        gridbar();

        // output linear: 8 N-tiles x 16 K-slices (K=64) = 128 units
        if (bid < 128) {
            int tn = bid >> 4, ks = bid & 15;
            gemm_tile(h1 + ks * 64, H_,
                      lin_w + (size_t)tn * 128 * H_ + ks * 64, H_,
                      d_part + (size_t)ks * B_ * O_ + tn * 128, O_, 64, As, Ws);
        }
        gridbar();
        for (int idx = bid * NT + tid; idx < B_ * O_; idx += NTHREADS) {
            int b = idx >> 10, n = idx & 1023;
            float v = lin_b[n];
#pragma unroll
            for (int s = 0; s < 16; s++)
                v += d_part[(size_t)s * B_ * O_ + (size_t)b * O_ + n];
            out[(size_t)b * T_ * O_ + (size_t)t * O_ + n] = v;
            d_x[idx] = v;
        }
        gridbar();
    }
}

// ---------------- driver: single launch => single graph node ----------------
extern "C" void kernel_launch(void* const* d_in, const int* in_sizes, int n_in,
                              void* d_out, int out_size)
{
    seq2seq_kernel<<<NB, NT>>>(
        (const float*)d_in[0], (const float*)d_in[1], (const float*)d_in[2],
        (const float*)d_in[3], (const float*)d_in[4], (const float*)d_in[5],
        (const float*)d_in[6], (const float*)d_in[7], (const float*)d_in[8],
        (float*)d_out);
}

// round 11
// speedup vs baseline: 2.7312x; 1.6392x over previous
#include <cuda_runtime.h>
#include <cuda_bf16.h>
#include <mma.h>
#include <math.h>
using namespace nvcuda;

// Fixed problem shapes
constexpr int S_ = 128, B_ = 64, I_ = 1024, H_ = 1024, O_ = 1024, T_ = 64;
constexpr int G_ = 4 * H_;          // 4096
constexpr int NB = 148;             // 1 CTA/SM, co-residency guaranteed
constexpr int NT = 512;
constexpr int NTHREADS = NB * NT;

// smem tiles (bf16): A 64x64 (hi+lo), W 256x64 (hi+lo), strides padded
constexpr int AS_ST = 72;
constexpr int WS_ST = 72;
constexpr int SMEM_BYTES = (2 * 64 * AS_ST + 2 * 256 * WS_ST) * 2;   // 92160

// split-weight storage offsets (elements)
constexpr size_t W_LAYER  = (size_t)G_ * I_;          // 4,194,304
constexpr size_t OFF_EWIH = 0;
constexpr size_t OFF_EWHH = 2 * W_LAYER;
constexpr size_t OFF_DWIH = 4 * W_LAYER;
constexpr size_t OFF_DWHH = 6 * W_LAYER;
constexpr size_t OFF_LIN  = 8 * W_LAYER;
constexpr size_t NW_TOT   = 8 * W_LAYER + (size_t)O_ * H_;

// ---------------- static device scratch ----------------
__device__ __nv_bfloat16 d_whi[NW_TOT];
__device__ __nv_bfloat16 d_wlo[NW_TOT];
__device__ float d_P[(size_t)S_ * B_ * G_];
__device__ float d_ys0[(size_t)S_ * B_ * H_];
__device__ float d_h[2 * B_ * H_];
__device__ float d_c[2 * B_ * H_];
__device__ float d_part[8 * B_ * G_];     // 8 slices x B x G (>= 16 x B x O)
__device__ float d_x[B_ * I_];
__device__ unsigned g_bar = 0;
__device__ unsigned g_gen = 0;

// ---------------- grid-wide barrier ----------------
__device__ __forceinline__ void gridbar() {
    __syncthreads();
    if (threadIdx.x == 0) {
        __threadfence();
        unsigned gen = *(volatile unsigned*)&g_gen;
        if (atomicAdd(&g_bar, 1) == NB - 1) {
            g_bar = 0;
            __threadfence();
            atomicAdd(&g_gen, 1);
        } else {
            while (*(volatile unsigned*)&g_gen == gen) { }
        }
        __threadfence();
    }
    __syncthreads();
}

__device__ __forceinline__ __nv_bfloat162 pack2(__nv_bfloat16 a, __nv_bfloat16 b) {
    __nv_bfloat162 t; t.x = a; t.y = b; return t;
}

// one-time (per launch) weight split: w = hi(bf16) + lo(bf16)
__device__ void split_w(const float* __restrict__ src, size_t off, size_t n) {
    for (size_t i = blockIdx.x * (size_t)NT + threadIdx.x; i < n; i += NTHREADS) {
        float v = src[i];
        __nv_bfloat16 h = __float2bfloat16(v);
        d_whi[off + i] = h;
        d_wlo[off + i] = __float2bfloat16(v - __bfloat162float(h));
    }
}

// ---------------- tensor-core tile: C[64 x 256] = A[64,K] @ W[256,K]^T ----------------
// bf16x3 compensated: acc += Ahi*Whi + Ahi*Wlo + Alo*Whi  (fp32 accum)
// 16 warps: 2 m-groups (32 rows) x 8 n-groups (32 cols); warp = 2x2 wmma frags.
__device__ void mma_tile(const float* __restrict__ A, int lda,
                         const __nv_bfloat16* __restrict__ Whi,
                         const __nv_bfloat16* __restrict__ Wlo, int ldw,
                         float* __restrict__ C, int ldc, int K,
                         __nv_bfloat16* As_hi, __nv_bfloat16* As_lo,
                         __nv_bfloat16* Ws_hi, __nv_bfloat16* Ws_lo)
{
    const int tid = threadIdx.x;
    const int w = tid >> 5;
    const int m0 = (w >> 3) * 32;       // 0 or 32
    const int n0 = (w & 7) * 32;        // 0..224

    wmma::fragment<wmma::accumulator, 16, 16, 16, float> acc[2][2];
#pragma unroll
    for (int i = 0; i < 2; i++)
#pragma unroll
        for (int j = 0; j < 2; j++) wmma::fill_fragment(acc[i][j], 0.f);

    for (int kb = 0; kb < K; kb += 64) {
        // stage A chunk 64x64 fp32 -> bf16 hi/lo
#pragma unroll
        for (int q = 0; q < 2; q++) {
            int v = tid + q * NT;
            int row = v >> 4, c4 = v & 15;
            float4 a = *reinterpret_cast<const float4*>(A + (size_t)row * lda + kb + c4 * 4);
            __nv_bfloat16 hx = __float2bfloat16(a.x), hy = __float2bfloat16(a.y);
            __nv_bfloat16 hz = __float2bfloat16(a.z), hw = __float2bfloat16(a.w);
            __nv_bfloat16 lx = __float2bfloat16(a.x - __bfloat162float(hx));
            __nv_bfloat16 ly = __float2bfloat16(a.y - __bfloat162float(hy));
            __nv_bfloat16 lz = __float2bfloat16(a.z - __bfloat162float(hz));
            __nv_bfloat16 lw = __float2bfloat16(a.w - __bfloat162float(hw));
            __nv_bfloat162* ph = reinterpret_cast<__nv_bfloat162*>(As_hi + row * AS_ST + c4 * 4);
            ph[0] = pack2(hx, hy); ph[1] = pack2(hz, hw);
            __nv_bfloat162* pl = reinterpret_cast<__nv_bfloat162*>(As_lo + row * AS_ST + c4 * 4);
            pl[0] = pack2(lx, ly); pl[1] = pack2(lz, lw);
        }
        // stage W chunk 256x64 bf16 hi/lo (pre-split in gmem)
#pragma unroll
        for (int q = 0; q < 4; q++) {
            int v = tid + q * NT;
            int row = v >> 3, c8 = v & 7;
            *reinterpret_cast<uint4*>(Ws_hi + row * WS_ST + c8 * 8) =
                *reinterpret_cast<const uint4*>(Whi + (size_t)row * ldw + kb + c8 * 8);
            *reinterpret_cast<uint4*>(Ws_lo + row * WS_ST + c8 * 8) =
                *reinterpret_cast<const uint4*>(Wlo + (size_t)row * ldw + kb + c8 * 8);
        }
        __syncthreads();

#pragma unroll
        for (int k16 = 0; k16 < 4; k16++) {
            wmma::fragment<wmma::matrix_a, 16, 16, 16, __nv_bfloat16, wmma::row_major> ahi[2], alo[2];
#pragma unroll
            for (int mi = 0; mi < 2; mi++) {
                wmma::load_matrix_sync(ahi[mi], As_hi + (m0 + mi * 16) * AS_ST + k16 * 16, AS_ST);
                wmma::load_matrix_sync(alo[mi], As_lo + (m0 + mi * 16) * AS_ST + k16 * 16, AS_ST);
            }
#pragma unroll
            for (int nf = 0; nf < 2; nf++) {
                wmma::fragment<wmma::matrix_b, 16, 16, 16, __nv_bfloat16, wmma::col_major> bhi, blo;
                wmma::load_matrix_sync(bhi, Ws_hi + (n0 + nf * 16) * WS_ST + k16 * 16, WS_ST);
                wmma::load_matrix_sync(blo, Ws_lo + (n0 + nf * 16) * WS_ST + k16 * 16, WS_ST);
#pragma unroll
                for (int mi = 0; mi < 2; mi++) {
                    wmma::mma_sync(acc[mi][nf], ahi[mi], bhi, acc[mi][nf]);
                    wmma::mma_sync(acc[mi][nf], ahi[mi], blo, acc[mi][nf]);
                    wmma::mma_sync(acc[mi][nf], alo[mi], bhi, acc[mi][nf]);
                }
            }
        }
        __syncthreads();
    }

#pragma unroll
    for (int mi = 0; mi < 2; mi++)
#pragma unroll
        for (int nf = 0; nf < 2; nf++)
            wmma::store_matrix_sync(C + (size_t)(m0 + mi * 16) * ldc + n0 + nf * 16,
                                    acc[mi][nf], ldc, wmma::mem_row_major);
}

__device__ __forceinline__ float sig_(float x) { return 1.f / (1.f + __expf(-x)); }

// pointwise LSTM gates: sum 8 split-K partials (+ optional precomputed input proj)
__device__ void gates_fn(const float* __restrict__ proj, const float* __restrict__ bias,
                         float* __restrict__ h, float* __restrict__ c,
                         float* __restrict__ ysave)
{
    for (int idx = blockIdx.x * NT + threadIdx.x; idx < B_ * H_; idx += NTHREADS) {
        int b = idx >> 10, n = idx & 1023;
        float gi = bias[n], gf = bias[H_ + n], gg = bias[2 * H_ + n], go = bias[3 * H_ + n];
        if (proj) {
            const float* p = proj + (size_t)b * G_;
            gi += p[n]; gf += p[H_ + n]; gg += p[2 * H_ + n]; go += p[3 * H_ + n];
        }
#pragma unroll
        for (int s = 0; s < 8; s++) {
            const float* p = d_part + (size_t)s * B_ * G_ + (size_t)b * G_;
            gi += p[n]; gf += p[H_ + n]; gg += p[2 * H_ + n]; go += p[3 * H_ + n];
        }
        float cv = sig_(gf) * c[idx] + sig_(gi) * tanhf(gg);
        float hv = sig_(go) * tanhf(cv);
        c[idx] = cv;
        h[idx] = hv;
        if (ysave) ysave[idx] = hv;
    }
}

// ---------------- whole seq2seq: ONE persistent kernel ----------------
__global__ void __launch_bounds__(NT)
seq2seq_kernel(const float* __restrict__ x_seq,
               const float* __restrict__ enc_wih, const float* __restrict__ enc_whh,
               const float* __restrict__ enc_b,
               const float* __restrict__ dec_wih, const float* __restrict__ dec_whh,
               const float* __restrict__ dec_b,
               const float* __restrict__ lin_w, const float* __restrict__ lin_b,
               float* __restrict__ out)
{
    extern __shared__ __nv_bfloat16 smem_bf[];
    __nv_bfloat16* As_hi = smem_bf;
    __nv_bfloat16* As_lo = As_hi + 64 * AS_ST;
    __nv_bfloat16* Ws_hi = As_lo + 64 * AS_ST;
    __nv_bfloat16* Ws_lo = Ws_hi + 256 * WS_ST;

    const int bid = blockIdx.x, tid = threadIdx.x;

    // one-time weight split (recomputed every launch: deterministic)
    split_w(enc_wih, OFF_EWIH, 2 * W_LAYER);
    split_w(enc_whh, OFF_EWHH, 2 * W_LAYER);
    split_w(dec_wih, OFF_DWIH, 2 * W_LAYER);
    split_w(dec_whh, OFF_DWHH, 2 * W_LAYER);
    split_w(lin_w,   OFF_LIN,  (size_t)O_ * H_);
    // init states + decoder x0
    for (int i = bid * NT + tid; i < 2 * B_ * H_; i += NTHREADS) { d_h[i] = 0.f; d_c[i] = 0.f; }
    for (int i = bid * NT + tid; i < B_ * I_; i += NTHREADS)
        d_x[i] = x_seq[(size_t)(S_ - 1) * B_ * I_ + i];
    gridbar();

    // ===== encoder: 2 stacked layers =====
    for (int l = 0; l < 2; l++) {
        const float* inp  = (l == 0) ? x_seq : d_ys0;
        const __nv_bfloat16* wih_hi = d_whi + OFF_EWIH + (size_t)l * W_LAYER;
        const __nv_bfloat16* wih_lo = d_wlo + OFF_EWIH + (size_t)l * W_LAYER;
        const __nv_bfloat16* whh_hi = d_whi + OFF_EWHH + (size_t)l * W_LAYER;
        const __nv_bfloat16* whh_lo = d_wlo + OFF_EWHH + (size_t)l * W_LAYER;
        const float* bias = enc_b + (size_t)l * G_;
        float* hl = d_h + l * B_ * H_;
        float* cl = d_c + l * B_ * H_;

        // batched input projection: 128 m-tiles x 16 n-tiles, K=1024
        for (int u = bid; u < 128 * 16; u += NB) {
            int tm = u >> 4, tn = u & 15;
            mma_tile(inp + (size_t)tm * 64 * I_, I_,
                     wih_hi + (size_t)tn * 256 * I_, wih_lo + (size_t)tn * 256 * I_, I_,
                     d_P + (size_t)tm * 64 * G_ + tn * 256, G_, I_,
                     As_hi, As_lo, Ws_hi, Ws_lo);
        }
        gridbar();

        // recurrence: 16 n-tiles x 8 k-slices (K=128) = 128 units
        for (int t = 0; t < S_; t++) {
            if (bid < 128) {
                int tn = bid >> 3, ks = bid & 7;
                mma_tile(hl + ks * 128, H_,
                         whh_hi + (size_t)tn * 256 * H_ + ks * 128,
                         whh_lo + (size_t)tn * 256 * H_ + ks * 128, H_,
                         d_part + (size_t)ks * B_ * G_ + tn * 256, G_, 128,
                         As_hi, As_lo, Ws_hi, Ws_lo);
            }
            gridbar();
            gates_fn(d_P + (size_t)t * B_ * G_, bias, hl, cl,
                     (l == 0) ? (d_ys0 + (size_t)t * B_ * H_) : nullptr);
            gridbar();
        }
    }

    // ===== autoregressive decoder =====
    float* h0 = d_h;             float* c0 = d_c;
    float* h1 = d_h + B_ * H_;   float* c1 = d_c + B_ * H_;

    for (int t = 0; t < T_; t++) {
#pragma unroll 1
        for (int l = 0; l < 2; l++) {
            const float* xin = (l == 0) ? d_x : h0;
            float* hl = (l == 0) ? h0 : h1;
            float* cl = (l == 0) ? c0 : c1;
            const size_t wih_off = OFF_DWIH + (size_t)l * W_LAYER;
            const size_t whh_off = OFF_DWHH + (size_t)l * W_LAYER;
            // virtual K=2048: slices 0-3 -> x part, 4-7 -> h part (K=256 each)
            if (bid < 128) {
                int tn = bid >> 3, ks = bid & 7;
                const float* Aptr;
                size_t woff;
                if (ks < 4) { Aptr = xin + ks * 256;
                              woff = wih_off + (size_t)tn * 256 * I_ + ks * 256; }
                else        { Aptr = hl + (ks - 4) * 256;
                              woff = whh_off + (size_t)tn * 256 * H_ + (ks - 4) * 256; }
                mma_tile(Aptr, 1024, d_whi + woff, d_wlo + woff, 1024,
                         d_part + (size_t)ks * B_ * G_ + tn * 256, G_, 256,
                         As_hi, As_lo, Ws_hi, Ws_lo);
            }
            gridbar();
            gates_fn(nullptr, dec_b + (size_t)l * G_, hl, cl, nullptr);
            gridbar();
        }

        // output linear: 4 n-tiles x 16 k-slices (K=64) = 64 units
        if (bid < 64) {
            int tn = bid >> 4, ks = bid & 15;
            const size_t woff = OFF_LIN + (size_t)tn * 256 * H_ + ks * 64;
            mma_tile(h1 + ks * 64, H_, d_whi + woff, d_wlo + woff, H_,
                     d_part + (size_t)ks * B_ * O_ + tn * 256, O_, 64,
                     As_hi, As_lo, Ws_hi, Ws_lo);
        }
        gridbar();
        for (int idx = bid * NT + tid; idx < B_ * O_; idx += NTHREADS) {
            int b = idx >> 10, n = idx & 1023;
            float v = lin_b[n];
#pragma unroll
            for (int s = 0; s < 16; s++)
                v += d_part[(size_t)s * B_ * O_ + (size_t)b * O_ + n];
            out[(size_t)b * T_ * O_ + (size_t)t * O_ + n] = v;
            d_x[idx] = v;
        }
        gridbar();
    }
}

// ---------------- driver: single launch => single graph node ----------------
extern "C" void kernel_launch(void* const* d_in, const int* in_sizes, int n_in,
                              void* d_out, int out_size)
{
    cudaFuncSetAttribute(seq2seq_kernel,
                         cudaFuncAttributeMaxDynamicSharedMemorySize, SMEM_BYTES);
    seq2seq_kernel<<<NB, NT, SMEM_BYTES>>>(
        (const float*)d_in[0], (const float*)d_in[1], (const float*)d_in[2],
        (const float*)d_in[3], (const float*)d_in[4], (const float*)d_in[5],
        (const float*)d_in[6], (const float*)d_in[7], (const float*)d_in[8],
        (float*)d_out);
}

// round 12
// speedup vs baseline: 2.9048x; 1.0635x over previous
#include <cuda_runtime.h>
#include <cuda_bf16.h>
#include <mma.h>
#include <math.h>
using namespace nvcuda;

// Fixed problem shapes
constexpr int S_ = 128, B_ = 64, I_ = 1024, H_ = 1024, O_ = 1024, T_ = 64;
constexpr int G_ = 4 * H_;          // 4096
constexpr int NB = 148;             // 1 CTA/SM, co-residency guaranteed
constexpr int NT = 512;
constexpr int NTHREADS = NB * NT;

// smem stage layout (bf16 elems): A hi/lo 64x72, W hi/lo 256x72
constexpr int AS_ST = 72, WS_ST = 72;
constexpr int A_HI = 0;
constexpr int A_LO = 64 * AS_ST;
constexpr int W_HI = 2 * 64 * AS_ST;
constexpr int W_LO = W_HI + 256 * WS_ST;
constexpr int STAGE_ELEMS = W_LO + 256 * WS_ST;          // 46080 elems
constexpr int SMEM_BYTES = 2 * STAGE_ELEMS * 2;          // 184320 B

// split-weight storage offsets (elements)
constexpr size_t W_LAYER  = (size_t)G_ * I_;
constexpr size_t OFF_EWIH = 0;
constexpr size_t OFF_EWHH = 2 * W_LAYER;
constexpr size_t OFF_DWIH = 4 * W_LAYER;
constexpr size_t OFF_DWHH = 6 * W_LAYER;
constexpr size_t OFF_LIN  = 8 * W_LAYER;
constexpr size_t NW_TOT   = 8 * W_LAYER + (size_t)O_ * H_;

// ---------------- static device scratch ----------------
__device__ __nv_bfloat16 d_whi[NW_TOT];
__device__ __nv_bfloat16 d_wlo[NW_TOT];
__device__ __nv_bfloat16 d_xs_hi[(size_t)S_ * B_ * I_];
__device__ __nv_bfloat16 d_xs_lo[(size_t)S_ * B_ * I_];
__device__ __nv_bfloat16 d_ys_hi[(size_t)S_ * B_ * H_];
__device__ __nv_bfloat16 d_ys_lo[(size_t)S_ * B_ * H_];
__device__ __nv_bfloat16 d_h_hi[2 * B_ * H_];
__device__ __nv_bfloat16 d_h_lo[2 * B_ * H_];
__device__ __nv_bfloat16 d_x_hi[B_ * I_];
__device__ __nv_bfloat16 d_x_lo[B_ * I_];
__device__ float d_c[2 * B_ * H_];
__device__ float d_P[(size_t)S_ * B_ * G_];
__device__ float d_part[8 * B_ * G_];     // 8 slices x B x G (>= 16 x B x O)
__device__ unsigned g_bar = 0;
__device__ unsigned g_gen = 0;

// ---------------- grid-wide barrier ----------------
__device__ __forceinline__ void gridbar() {
    __syncthreads();
    if (threadIdx.x == 0) {
        __threadfence();
        unsigned gen = *(volatile unsigned*)&g_gen;
        if (atomicAdd(&g_bar, 1) == NB - 1) {
            g_bar = 0;
            __threadfence();
            atomicAdd(&g_gen, 1);
        } else {
            while (*(volatile unsigned*)&g_gen == gen) { }
        }
        __threadfence();
    }
    __syncthreads();
}

// ---------------- cp.async helpers ----------------
__device__ __forceinline__ void cpa16(void* dst, const void* src) {
    unsigned d = (unsigned)__cvta_generic_to_shared(dst);
    asm volatile("cp.async.ca.shared.global [%0], [%1], 16;" :: "r"(d), "l"(src));
}
__device__ __forceinline__ void cpa_commit() {
    asm volatile("cp.async.commit_group;");
}

// stage one 64-K chunk: A(64 rows) + W(256 rows), hi+lo, 10 cp.async per thread
__device__ __forceinline__ void stage_chunk(
    __nv_bfloat16* sb,
    const __nv_bfloat16* __restrict__ Ahi, const __nv_bfloat16* __restrict__ Alo, int lda,
    const __nv_bfloat16* __restrict__ Whi, const __nv_bfloat16* __restrict__ Wlo, int ldw,
    int kb)
{
    const int tid = threadIdx.x;
    const int ar = tid >> 3, ac = (tid & 7) * 8;
    cpa16(sb + A_HI + ar * AS_ST + ac, Ahi + (size_t)ar * lda + kb + ac);
    cpa16(sb + A_LO + ar * AS_ST + ac, Alo + (size_t)ar * lda + kb + ac);
#pragma unroll
    for (int q = 0; q < 4; q++) {
        int v = tid + q * NT;
        int wr = v >> 3, wc = (v & 7) * 8;
        cpa16(sb + W_HI + wr * WS_ST + wc, Whi + (size_t)wr * ldw + kb + wc);
        cpa16(sb + W_LO + wr * WS_ST + wc, Wlo + (size_t)wr * ldw + kb + wc);
    }
}

// ---------------- tensor tile: C[64 x 256] = A[64,K] @ W[256,K]^T ----------------
// bf16x3 compensated: acc += Ahi*Whi + Ahi*Wlo + Alo*Whi (fp32 accum).
// Operands pre-split bf16 hi/lo in gmem; cp.async double-buffered staging.
__device__ void mma_tile(
    const __nv_bfloat16* __restrict__ Ahi, const __nv_bfloat16* __restrict__ Alo, int lda,
    const __nv_bfloat16* __restrict__ Whi, const __nv_bfloat16* __restrict__ Wlo, int ldw,
    float* __restrict__ C, int ldc, int K, __nv_bfloat16* sm)
{
    const int w = threadIdx.x >> 5;
    const int m0 = (w >> 3) * 32;       // 0 or 32
    const int n0 = (w & 7) * 32;        // 0..224

    wmma::fragment<wmma::accumulator, 16, 16, 16, float> acc[2][2];
#pragma unroll
    for (int i = 0; i < 2; i++)
#pragma unroll
        for (int j = 0; j < 2; j++) wmma::fill_fragment(acc[i][j], 0.f);

    const int nch = K >> 6;
    stage_chunk(sm, Ahi, Alo, lda, Whi, Wlo, ldw, 0);
    cpa_commit();
    if (nch > 1) {
        stage_chunk(sm + STAGE_ELEMS, Ahi, Alo, lda, Whi, Wlo, ldw, 64);
        cpa_commit();
    }

    for (int i = 0; i < nch; i++) {
        if (i + 1 < nch) asm volatile("cp.async.wait_group 1;");
        else             asm volatile("cp.async.wait_group 0;");
        __syncthreads();

        const __nv_bfloat16* sb = sm + (i & 1) * STAGE_ELEMS;
#pragma unroll
        for (int k16 = 0; k16 < 4; k16++) {
            wmma::fragment<wmma::matrix_a, 16, 16, 16, __nv_bfloat16, wmma::row_major> ahi[2], alo[2];
#pragma unroll
            for (int mi = 0; mi < 2; mi++) {
                wmma::load_matrix_sync(ahi[mi], sb + A_HI + (m0 + mi * 16) * AS_ST + k16 * 16, AS_ST);
                wmma::load_matrix_sync(alo[mi], sb + A_LO + (m0 + mi * 16) * AS_ST + k16 * 16, AS_ST);
            }
#pragma unroll
            for (int nf = 0; nf < 2; nf++) {
                wmma::fragment<wmma::matrix_b, 16, 16, 16, __nv_bfloat16, wmma::col_major> bhi, blo;
                wmma::load_matrix_sync(bhi, sb + W_HI + (n0 + nf * 16) * WS_ST + k16 * 16, WS_ST);
                wmma::load_matrix_sync(blo, sb + W_LO + (n0 + nf * 16) * WS_ST + k16 * 16, WS_ST);
#pragma unroll
                for (int mi = 0; mi < 2; mi++) {
                    wmma::mma_sync(acc[mi][nf], ahi[mi], bhi, acc[mi][nf]);
                    wmma::mma_sync(acc[mi][nf], ahi[mi], blo, acc[mi][nf]);
                    wmma::mma_sync(acc[mi][nf], alo[mi], bhi, acc[mi][nf]);
                }
            }
        }
        __syncthreads();

        if (i + 2 < nch) {
            stage_chunk(sm + (i & 1) * STAGE_ELEMS, Ahi, Alo, lda, Whi, Wlo, ldw, (i + 2) * 64);
            cpa_commit();
        }
    }

#pragma unroll
    for (int mi = 0; mi < 2; mi++)
#pragma unroll
        for (int nf = 0; nf < 2; nf++)
            wmma::store_matrix_sync(C + (size_t)(m0 + mi * 16) * ldc + n0 + nf * 16,
                                    acc[mi][nf], ldc, wmma::mem_row_major);
}

// one-time (per launch) weight split: w = hi(bf16) + lo(bf16)
__device__ void split_w(const float* __restrict__ src, size_t off, size_t n) {
    for (size_t i = blockIdx.x * (size_t)NT + threadIdx.x; i < n; i += NTHREADS) {
        float v = src[i];
        __nv_bfloat16 h = __float2bfloat16(v);
        d_whi[off + i] = h;
        d_wlo[off + i] = __float2bfloat16(v - __bfloat162float(h));
    }
}

__device__ __forceinline__ float sig_(float x) { return 1.f / (1.f + __expf(-x)); }

// pointwise LSTM gates: sum 8 split-K partials (+ optional proj); emit h as bf16 hi/lo
__device__ void gates_fn(const float* __restrict__ proj, const float* __restrict__ bias,
                         __nv_bfloat16* __restrict__ h_hi, __nv_bfloat16* __restrict__ h_lo,
                         float* __restrict__ c,
                         __nv_bfloat16* __restrict__ ys_hi, __nv_bfloat16* __restrict__ ys_lo)
{
    for (int idx = blockIdx.x * NT + threadIdx.x; idx < B_ * H_; idx += NTHREADS) {
        int b = idx >> 10, n = idx & 1023;
        float gi = bias[n], gf = bias[H_ + n], gg = bias[2 * H_ + n], go = bias[3 * H_ + n];
        if (proj) {
            const float* p = proj + (size_t)b * G_;
            gi += p[n]; gf += p[H_ + n]; gg += p[2 * H_ + n]; go += p[3 * H_ + n];
        }
#pragma unroll
        for (int s = 0; s < 8; s++) {
            const float* p = d_part + (size_t)s * B_ * G_ + (size_t)b * G_;
            gi += p[n]; gf += p[H_ + n]; gg += p[2 * H_ + n]; go += p[3 * H_ + n];
        }
        float cv = sig_(gf) * c[idx] + sig_(gi) * tanhf(gg);
        float hv = sig_(go) * tanhf(cv);
        c[idx] = cv;
        __nv_bfloat16 hh = __float2bfloat16(hv);
        __nv_bfloat16 hl = __float2bfloat16(hv - __bfloat162float(hh));
        h_hi[idx] = hh; h_lo[idx] = hl;
        if (ys_hi) { ys_hi[idx] = hh; ys_lo[idx] = hl; }
    }
}

// ---------------- whole seq2seq: ONE persistent kernel ----------------
__global__ void __launch_bounds__(NT)
seq2seq_kernel(const float* __restrict__ x_seq,
               const float* __restrict__ enc_wih, const float* __restrict__ enc_whh,
               const float* __restrict__ enc_b,
               const float* __restrict__ dec_wih, const float* __restrict__ dec_whh,
               const float* __restrict__ dec_b,
               const float* __restrict__ lin_w, const float* __restrict__ lin_b,
               float* __restrict__ out)
{
    extern __shared__ __align__(16) __nv_bfloat16 sm[];
    const int bid = blockIdx.x, tid = threadIdx.x;

    // one-time splits (recomputed every launch: deterministic)
    split_w(enc_wih, OFF_EWIH, 2 * W_LAYER);
    split_w(enc_whh, OFF_EWHH, 2 * W_LAYER);
    split_w(dec_wih, OFF_DWIH, 2 * W_LAYER);
    split_w(dec_whh, OFF_DWHH, 2 * W_LAYER);
    split_w(lin_w,   OFF_LIN,  (size_t)O_ * H_);
    for (size_t i = bid * (size_t)NT + tid; i < (size_t)S_ * B_ * I_; i += NTHREADS) {
        float v = x_seq[i];
        __nv_bfloat16 h = __float2bfloat16(v);
        d_xs_hi[i] = h;
        d_xs_lo[i] = __float2bfloat16(v - __bfloat162float(h));
    }
    for (int i = bid * NT + tid; i < 2 * B_ * H_; i += NTHREADS) {
        d_h_hi[i] = __float2bfloat16(0.f); d_h_lo[i] = __float2bfloat16(0.f);
        d_c[i] = 0.f;
    }
    for (int i = bid * NT + tid; i < B_ * I_; i += NTHREADS) {
        float v = x_seq[(size_t)(S_ - 1) * B_ * I_ + i];
        __nv_bfloat16 h = __float2bfloat16(v);
        d_x_hi[i] = h;
        d_x_lo[i] = __float2bfloat16(v - __bfloat162float(h));
    }
    gridbar();

    // ===== encoder: 2 stacked layers =====
    for (int l = 0; l < 2; l++) {
        const __nv_bfloat16* in_hi = (l == 0) ? d_xs_hi : d_ys_hi;
        const __nv_bfloat16* in_lo = (l == 0) ? d_xs_lo : d_ys_lo;
        const __nv_bfloat16* wih_hi = d_whi + OFF_EWIH + (size_t)l * W_LAYER;
        const __nv_bfloat16* wih_lo = d_wlo + OFF_EWIH + (size_t)l * W_LAYER;
        const __nv_bfloat16* whh_hi = d_whi + OFF_EWHH + (size_t)l * W_LAYER;
        const __nv_bfloat16* whh_lo = d_wlo + OFF_EWHH + (size_t)l * W_LAYER;
        const float* bias = enc_b + (size_t)l * G_;
        __nv_bfloat16* hl_hi = d_h_hi + l * B_ * H_;
        __nv_bfloat16* hl_lo = d_h_lo + l * B_ * H_;
        float* cl = d_c + l * B_ * H_;

        // batched input projection: 128 m-tiles x 16 n-tiles, K=1024
        for (int u = bid; u < 128 * 16; u += NB) {
            int tm = u >> 4, tn = u & 15;
            mma_tile(in_hi + (size_t)tm * 64 * I_, in_lo + (size_t)tm * 64 * I_, I_,
                     wih_hi + (size_t)tn * 256 * I_, wih_lo + (size_t)tn * 256 * I_, I_,
                     d_P + (size_t)tm * 64 * G_ + tn * 256, G_, I_, sm);
        }
        gridbar();

        // recurrence: 16 n-tiles x 8 k-slices (K=128) = 128 units
        for (int t = 0; t < S_; t++) {
            if (bid < 128) {
                int tn = bid >> 3, ks = bid & 7;
                mma_tile(hl_hi + ks * 128, hl_lo + ks * 128, H_,
                         whh_hi + (size_t)tn * 256 * H_ + ks * 128,
                         whh_lo + (size_t)tn * 256 * H_ + ks * 128, H_,
                         d_part + (size_t)ks * B_ * G_ + tn * 256, G_, 128, sm);
            }
            gridbar();
            gates_fn(d_P + (size_t)t * B_ * G_, bias, hl_hi, hl_lo, cl,
                     (l == 0) ? (d_ys_hi + (size_t)t * B_ * H_) : nullptr,
                     (l == 0) ? (d_ys_lo + (size_t)t * B_ * H_) : nullptr);
            gridbar();
        }
    }

    // ===== autoregressive decoder =====
    __nv_bfloat16* h0_hi = d_h_hi;            __nv_bfloat16* h0_lo = d_h_lo;
    __nv_bfloat16* h1_hi = d_h_hi + B_ * H_;  __nv_bfloat16* h1_lo = d_h_lo + B_ * H_;
    float* c0 = d_c;
    float* c1 = d_c + B_ * H_;

    for (int t = 0; t < T_; t++) {
#pragma unroll 1
        for (int l = 0; l < 2; l++) {
            const __nv_bfloat16* xin_hi = (l == 0) ? d_x_hi : h0_hi;
            const __nv_bfloat16* xin_lo = (l == 0) ? d_x_lo : h0_lo;
            __nv_bfloat16* hl_hi = (l == 0) ? h0_hi : h1_hi;
            __nv_bfloat16* hl_lo = (l == 0) ? h0_lo : h1_lo;
            float* cl = (l == 0) ? c0 : c1;
            const size_t wih_off = OFF_DWIH + (size_t)l * W_LAYER;
            const size_t whh_off = OFF_DWHH + (size_t)l * W_LAYER;
            // virtual K=2048: slices 0-3 -> x part, 4-7 -> h part (K=256 each)
            if (bid < 128) {
                int tn = bid >> 3, ks = bid & 7;
                const __nv_bfloat16* Ah; const __nv_bfloat16* Al;
                size_t woff;
                if (ks < 4) { Ah = xin_hi + ks * 256; Al = xin_lo + ks * 256;
                              woff = wih_off + (size_t)tn * 256 * I_ + ks * 256; }
                else        { Ah = hl_hi + (ks - 4) * 256; Al = hl_lo + (ks - 4) * 256;
                              woff = whh_off + (size_t)tn * 256 * H_ + (ks - 4) * 256; }
                mma_tile(Ah, Al, 1024, d_whi + woff, d_wlo + woff, 1024,
                         d_part + (size_t)ks * B_ * G_ + tn * 256, G_, 256, sm);
            }
            gridbar();
            gates_fn(nullptr, dec_b + (size_t)l * G_, hl_hi, hl_lo, cl, nullptr, nullptr);
            gridbar();
        }

        // output linear: 4 n-tiles x 16 k-slices (K=64) = 64 units
        if (bid < 64) {
            int tn = bid >> 4, ks = bid & 15;
            const size_t woff = OFF_LIN + (size_t)tn * 256 * H_ + ks * 64;
            mma_tile(h1_hi + ks * 64, h1_lo + ks * 64, H_,
                     d_whi + woff, d_wlo + woff, H_,
                     d_part + (size_t)ks * B_ * O_ + tn * 256, O_, 64, sm);
        }
        gridbar();
        for (int idx = bid * NT + tid; idx < B_ * O_; idx += NTHREADS) {
            int b = idx >> 10, n = idx & 1023;
            float v = lin_b[n];
#pragma unroll
            for (int s = 0; s < 16; s++)
                v += d_part[(size_t)s * B_ * O_ + (size_t)b * O_ + n];
            out[(size_t)b * T_ * O_ + (size_t)t * O_ + n] = v;
            __nv_bfloat16 hh = __float2bfloat16(v);
            d_x_hi[idx] = hh;
            d_x_lo[idx] = __float2bfloat16(v - __bfloat162float(hh));
        }
        gridbar();
    }
}

// ---------------- driver: single launch => single graph node ----------------
extern "C" void kernel_launch(void* const* d_in, const int* in_sizes, int n_in,
                              void* d_out, int out_size)
{
    cudaFuncSetAttribute(seq2seq_kernel,
                         cudaFuncAttributeMaxDynamicSharedMemorySize, SMEM_BYTES);
    seq2seq_kernel<<<NB, NT, SMEM_BYTES>>>(
        (const float*)d_in[0], (const float*)d_in[1], (const float*)d_in[2],
        (const float*)d_in[3], (const float*)d_in[4], (const float*)d_in[5],
        (const float*)d_in[6], (const float*)d_in[7], (const float*)d_in[8],
        (float*)d_out);
}